// round 5
// baseline (speedup 1.0000x reference)
#include <cuda_runtime.h>
#include <cuda_bf16.h>
#include <cstdint>
#include <cfloat>

// Problem constants (fixed by the reference)
#define NW        4
#define CCH       32
#define MPW       8
#define IMG_H     1024
#define IMG_W     1024
#define HW        (IMG_H * IMG_W)
#define WIN_H     512
#define WIN_W     512
#define SLOT_DIM  64
#define SIM_THRESH 0.1f
#define P_MAX     304

#define CHUNK     2048       // pixels per block in main kernel (8KB)
#define PPT       8          // pixels per thread (CHUNK/256)
#define NSTAGE    4          // bulk-load ring depth (stages = channels in flight)

// Scratch (device globals; no runtime allocation allowed)
__device__ unsigned d_edge16[16];   // [window*4 + edge] channel bitmask
__device__ int      d_map[CCH];

__device__ __forceinline__ uint32_t smem_u32(const void* p) {
    return (uint32_t)__cvta_generic_to_shared(p);
}

__device__ __forceinline__ void mbar_wait_parity(uint32_t mbar, uint32_t parity) {
    asm volatile(
        "{\n\t"
        ".reg .pred P1;\n\t"
        "WAIT_LOOP_%=:\n\t"
        "mbarrier.try_wait.parity.acquire.cta.shared::cta.b64 P1, [%0], %1, 0x989680;\n\t"
        "@P1 bra.uni WAIT_DONE_%=;\n\t"
        "bra.uni WAIT_LOOP_%=;\n\t"
        "WAIT_DONE_%=:\n\t"
        "}"
        :: "r"(mbar), "r"(parity) : "memory");
}

// ---------------------------------------------------------------------------
// K1: edge flags. 16 blocks (window,edge) x 512 threads (one per edge pixel).
// All 32 channel loads issued independently up front (MLP=32), then argmax.
// Unconditional per-block result write -> no init kernel, no atomics.
// ---------------------------------------------------------------------------
__global__ void __launch_bounds__(512) edge_kernel(
    const float* __restrict__ masks,
    const int* __restrict__ pad_left,
    const int* __restrict__ pad_top)
{
    const int ei = blockIdx.x;
    const int w  = ei >> 2;
    const int e  = ei & 3;            // 0=L 1=R 2=T 3=B

    int pl = pad_left[w], pt = pad_top[w];
    int ys = max(pt, 0), ye = min(pt + WIN_H, IMG_H);
    int xs = max(pl, 0), xe = min(pl + WIN_W, IMG_W);

    unsigned bit = 0u;
    if (ys < ye && xs < xe) {
        int len = (e < 2) ? (ye - ys) : (xe - xs);
        int k = threadIdx.x;
        if (k < len) {
            int y, x;
            if      (e == 0) { y = ys + k; x = xs;     }
            else if (e == 1) { y = ys + k; x = xe - 1; }
            else if (e == 2) { y = ys;     x = xs + k; }
            else             { y = ye - 1; x = xs + k; }
            const float* p = masks + (size_t)y * IMG_W + x;
            float v[CCH];
            #pragma unroll
            for (int c = 0; c < CCH; c++)            // 32 independent loads
                v[c] = __ldg(p + (size_t)c * HW);
            float best = v[0];
            int id = 0;
            #pragma unroll
            for (int c = 1; c < CCH; c++)
                if (v[c] > best) { best = v[c]; id = c; }
            if ((id >> 3) == w) bit = 1u << id;
        }
    }

    unsigned wm = __reduce_or_sync(0xffffffffu, bit);
    __shared__ unsigned sm[16];
    if ((threadIdx.x & 31) == 0) sm[threadIdx.x >> 5] = wm;
    __syncthreads();
    if (threadIdx.x == 0) {
        unsigned a = 0;
        #pragma unroll
        for (int i = 0; i < 16; i++) a |= sm[i];
        d_edge16[ei] = a;
    }
}

// ---------------------------------------------------------------------------
// K2: one block. Adjacency + candidate pairs, cosine sims, sequential merge
// scan -> 32-entry channel remap table.
// ---------------------------------------------------------------------------
__global__ void __launch_bounds__(256) map_kernel(
    const float* __restrict__ sf,
    const int* __restrict__ pad_left,
    const int* __restrict__ pad_top)
{
    __shared__ int  s_ci[P_MAX];
    __shared__ int  s_cj[P_MAX];
    __shared__ char s_hz[P_MAX];
    __shared__ char s_pass[P_MAX];
    __shared__ int  s_P;
    __shared__ unsigned s_edge[NW][4];

    if (threadIdx.x < 16)
        s_edge[threadIdx.x >> 2][threadIdx.x & 3] = d_edge16[threadIdx.x];

    if (threadIdx.x == 0) {
        int pl[NW], pt[NW];
        for (int i = 0; i < NW; i++) { pl[i] = pad_left[i]; pt[i] = pad_top[i]; }

        int na = 0;
        int ai[12], aj[12]; char ah[12];
        for (int i = 0; i < NW; i++) {
            for (int j = i + 1; j < NW; j++) {
                if (pt[i] == pt[j] && abs(pl[i] - pl[j]) == WIN_W) {
                    if (pl[i] < pl[j]) { ai[na] = i; aj[na] = j; }
                    else               { ai[na] = j; aj[na] = i; }
                    ah[na] = 1; na++;
                }
                if (pl[i] == pl[j] && abs(pt[i] - pt[j]) == WIN_H) {
                    if (pt[i] < pt[j]) { ai[na] = i; aj[na] = j; }
                    else               { ai[na] = j; aj[na] = i; }
                    ah[na] = 0; na++;
                }
            }
        }
        int P = 0;
        for (int a = 0; a < na; a++) {
            int si = ai[a] * MPW, sj = aj[a] * MPW;
            for (int ci = si + 1; ci < si + MPW; ci++)
                for (int cj = sj + 1; cj < sj + MPW; cj++) {
                    s_ci[P] = ci; s_cj[P] = cj; s_hz[P] = ah[a]; P++;
                }
        }
        s_P = P;
    }
    __syncthreads();

    int P = s_P;
    for (int p = threadIdx.x; p < P; p += blockDim.x) {
        int ci = s_ci[p], cj = s_cj[p];
        int wi = ci / MPW, wj = cj / MPW;
        int ri = ci % MPW - 1, rj = cj % MPW - 1;
        const float* fi = sf + ((long long)wi * (MPW - 1) + ri) * SLOT_DIM;
        const float* fj = sf + ((long long)wj * (MPW - 1) + rj) * SLOT_DIM;
        float dot = 0.f, ni = 0.f, nj = 0.f;
        #pragma unroll
        for (int k = 0; k < SLOT_DIM; k++) {
            float a = fi[k], b = fj[k];
            dot += a * b; ni += a * a; nj += b * b;
        }
        float sim = dot / ((sqrtf(ni) + 1e-8f) * (sqrtf(nj) + 1e-8f));

        bool ok;
        if (s_hz[p]) {
            ok = ((s_edge[wi][1] >> ci) & 1u) && ((s_edge[wj][0] >> cj) & 1u);
        } else {
            ok = ((s_edge[wi][3] >> ci) & 1u) && ((s_edge[wj][2] >> cj) & 1u);
        }
        s_pass[p] = (ok && sim > SIM_THRESH) ? 1 : 0;
    }
    __syncthreads();

    if (threadIdx.x == 0) {
        int mp[CCH];
        bool merged[CCH];
        for (int c = 0; c < CCH; c++) { mp[c] = c; merged[c] = false; }
        for (int p = 0; p < P; p++) {
            int ci = s_ci[p], cj = s_cj[p];
            if (s_pass[p] && !merged[ci] && !merged[cj]) {
                int keep = min(ci, cj), rem = max(ci, cj);
                for (int c = 0; c < CCH; c++)
                    if (mp[c] == rem) mp[c] = keep;
                merged[rem] = true;
            }
        }
        for (int c = 0; c < CCH; c++) d_map[c] = mp[c];
    }
}

// ---------------------------------------------------------------------------
// K3: fused main pass.
// Reads: 4-stage cp.async.bulk ring (one 8KB bulk copy per channel per block,
//        mbarrier completion) -> bypasses per-thread LSU/L1tex path.
// Compute: argmax over 32 channels from SMEM (LDS.128), remap via d_map.
// Writes: per-channel SMEM staging + double-buffered cp.async.bulk stores.
// ---------------------------------------------------------------------------
__global__ void __launch_bounds__(256) main_kernel(
    const float* __restrict__ masks,
    float* __restrict__ out)
{
    extern __shared__ __align__(16) float dsm[];
    float* sin  = dsm;                    // NSTAGE * CHUNK floats (32KB)
    float* sout = dsm + NSTAGE * CHUNK;   // 2 * CHUNK floats (16KB)

    __shared__ __align__(8) uint64_t mbar[NSTAGE];
    __shared__ int smap[CCH];

    const int t = threadIdx.x;
    if (t < CCH) smap[t] = d_map[t];
    if (t == 0) {
        #pragma unroll
        for (int s = 0; s < NSTAGE; s++) {
            uint32_t mb = smem_u32(&mbar[s]);
            asm volatile("mbarrier.init.shared.b64 [%0], %1;"
                         :: "r"(mb), "r"(1u) : "memory");
        }
        asm volatile("fence.proxy.async.shared::cta;" ::: "memory");
    }
    __syncthreads();

    const size_t base = (size_t)blockIdx.x * CHUNK;

    // prologue: issue first NSTAGE channel loads
    if (t == 0) {
        #pragma unroll
        for (int s = 0; s < NSTAGE; s++) {
            uint32_t mb = smem_u32(&mbar[s]);
            uint32_t ds = smem_u32(sin + s * CHUNK);
            const float* src = masks + (size_t)s * HW + base;
            asm volatile("mbarrier.arrive.expect_tx.shared.b64 _, [%0], %1;"
                         :: "r"(mb), "r"((unsigned)(CHUNK * 4)) : "memory");
            asm volatile(
                "cp.async.bulk.shared::cluster.global.mbarrier::complete_tx::bytes "
                "[%0], [%1], %2, [%3];"
                :: "r"(ds), "l"(src), "r"((unsigned)(CHUNK * 4)), "r"(mb) : "memory");
        }
    }

    float best[PPT];
    int   ida[PPT];
    #pragma unroll
    for (int i = 0; i < PPT; i++) { best[i] = -INFINITY; ida[i] = 0; }

    for (int c = 0; c < CCH; c++) {
        int s = c & (NSTAGE - 1);
        uint32_t ph = (unsigned)(c / NSTAGE) & 1u;
        mbar_wait_parity(smem_u32(&mbar[s]), ph);

        const float4* p = (const float4*)(sin + s * CHUNK + t * PPT);
        float4 a = p[0], b = p[1];
        float v[PPT] = {a.x, a.y, a.z, a.w, b.x, b.y, b.z, b.w};
        #pragma unroll
        for (int i = 0; i < PPT; i++)
            if (v[i] > best[i]) { best[i] = v[i]; ida[i] = c; }

        __syncthreads();   // everyone consumed stage s
        int cn = c + NSTAGE;
        if (t == 0 && cn < CCH) {
            uint32_t mb = smem_u32(&mbar[s]);
            uint32_t ds = smem_u32(sin + s * CHUNK);
            const float* src = masks + (size_t)cn * HW + base;
            asm volatile("mbarrier.arrive.expect_tx.shared.b64 _, [%0], %1;"
                         :: "r"(mb), "r"((unsigned)(CHUNK * 4)) : "memory");
            asm volatile(
                "cp.async.bulk.shared::cluster.global.mbarrier::complete_tx::bytes "
                "[%0], [%1], %2, [%3];"
                :: "r"(ds), "l"(src), "r"((unsigned)(CHUNK * 4)), "r"(mb) : "memory");
        }
    }

    #pragma unroll
    for (int i = 0; i < PPT; i++) ida[i] = smap[ida[i]];

    // staged one-hot writes, double-buffered bulk stores
    for (int c = 0; c < CCH; c++) {
        int buf = c & 1;
        if (c >= 2) {
            if (t == 0)
                asm volatile("cp.async.bulk.wait_group.read 1;" ::: "memory");
            __syncthreads();
        }
        float4* sb4 = (float4*)(sout + buf * CHUNK + t * PPT);
        float4 o1, o2;
        o1.x = (ida[0] == c) ? 1.0f : 0.0f;
        o1.y = (ida[1] == c) ? 1.0f : 0.0f;
        o1.z = (ida[2] == c) ? 1.0f : 0.0f;
        o1.w = (ida[3] == c) ? 1.0f : 0.0f;
        o2.x = (ida[4] == c) ? 1.0f : 0.0f;
        o2.y = (ida[5] == c) ? 1.0f : 0.0f;
        o2.z = (ida[6] == c) ? 1.0f : 0.0f;
        o2.w = (ida[7] == c) ? 1.0f : 0.0f;
        sb4[0] = o1; sb4[1] = o2;
        __syncthreads();
        if (t == 0) {
            float* gdst = out + (size_t)c * HW + base;
            uint32_t saddr = smem_u32(sout + buf * CHUNK);
            asm volatile("fence.proxy.async.shared::cta;" ::: "memory");
            asm volatile(
                "cp.async.bulk.global.shared::cta.bulk_group [%0], [%1], %2;"
                :: "l"(gdst), "r"(saddr), "n"(CHUNK * 4) : "memory");
            asm volatile("cp.async.bulk.commit_group;" ::: "memory");
        }
    }
    if (t == 0)
        asm volatile("cp.async.bulk.wait_group.read 0;" ::: "memory");
    __syncthreads();
}

// ---------------------------------------------------------------------------
extern "C" void kernel_launch(void* const* d_in, const int* in_sizes, int n_in,
                              void* d_out, int out_size)
{
    const float* masks = (const float*)d_in[0];
    const float* sf    = (const float*)d_in[1];
    const int*   pl    = (const int*)d_in[2];
    const int*   pt    = (const int*)d_in[3];
    float*       out   = (float*)d_out;

    static bool configured = false;
    if (!configured) {
        cudaFuncSetAttribute(main_kernel,
                             cudaFuncAttributeMaxDynamicSharedMemorySize,
                             (NSTAGE + 2) * CHUNK * 4);
        configured = true;
    }

    edge_kernel<<<16, 512>>>(masks, pl, pt);
    map_kernel<<<1, 256>>>(sf, pl, pt);
    main_kernel<<<HW / CHUNK, 256, (NSTAGE + 2) * CHUNK * 4>>>(masks, out);
}

// round 6
// speedup vs baseline: 1.4331x; 1.4331x over previous
#include <cuda_runtime.h>
#include <cuda_bf16.h>
#include <cstdint>
#include <cfloat>

// Problem constants (fixed by the reference)
#define NW        4
#define CCH       32
#define MPW       8
#define IMG_H     1024
#define IMG_W     1024
#define HW        (IMG_H * IMG_W)
#define WIN_H     512
#define WIN_W     512
#define SLOT_DIM  64
#define SIM_THRESH 0.1f
#define P_MAX     304

#define CHUNK     2048       // pixels per block (8KB per channel)
#define PPT       8          // pixels per consumer thread (CHUNK/256)
#define NSTAGE    8          // bulk-load ring depth
#define NCONS     256        // consumer threads
#define NTHR      288        // consumers + 1 producer warp

// Scratch (device globals; no runtime allocation allowed)
__device__ unsigned d_edge_q[NW][4][4];   // [window][edge][quarter] bitmasks
__device__ int      d_map[CCH];

__device__ __forceinline__ uint32_t smem_u32(const void* p) {
    return (uint32_t)__cvta_generic_to_shared(p);
}

__device__ __forceinline__ void mbar_wait(uint32_t mbar, uint32_t parity) {
    asm volatile(
        "{\n\t"
        ".reg .pred P1;\n\t"
        "WAIT_LOOP_%=:\n\t"
        "mbarrier.try_wait.parity.acquire.cta.shared::cta.b64 P1, [%0], %1, 0x989680;\n\t"
        "@P1 bra.uni WAIT_DONE_%=;\n\t"
        "bra.uni WAIT_LOOP_%=;\n\t"
        "WAIT_DONE_%=:\n\t"
        "}"
        :: "r"(mbar), "r"(parity) : "memory");
}

// ---------------------------------------------------------------------------
// K1: edge flags (R3 version - best measured). 64 blocks: (window,edge,quarter).
// ---------------------------------------------------------------------------
__global__ void __launch_bounds__(128) edge_kernel(
    const float* __restrict__ masks,
    const int* __restrict__ pad_left,
    const int* __restrict__ pad_top)
{
    int q  = blockIdx.x & 3;
    int we = blockIdx.x >> 2;
    int w  = we >> 2;
    int e  = we & 3;            // 0=L 1=R 2=T 3=B

    int pl = pad_left[w], pt = pad_top[w];
    int ys = max(pt, 0), ye = min(pt + WIN_H, IMG_H);
    int xs = max(pl, 0), xe = min(pl + WIN_W, IMG_W);

    unsigned mybit = 0u;
    if (ys < ye && xs < xe) {
        int len = (e < 2) ? (ye - ys) : (xe - xs);
        int k = q * 128 + threadIdx.x;
        if (k < len) {
            int y, x;
            if      (e == 0) { y = ys + k; x = xs;     }
            else if (e == 1) { y = ys + k; x = xe - 1; }
            else if (e == 2) { y = ys;     x = xs + k; }
            else             { y = ye - 1; x = xs + k; }
            const float* p = masks + (long long)y * IMG_W + x;
            float best = __ldg(p);
            int id = 0;
            #pragma unroll
            for (int c = 1; c < CCH; c++) {
                float v = __ldg(p + (long long)c * HW);
                if (v > best) { best = v; id = c; }
            }
            if ((id >> 3) == w) mybit = 1u << id;
        }
    }

    unsigned wm = __reduce_or_sync(0xffffffffu, mybit);
    __shared__ unsigned sm[4];
    if ((threadIdx.x & 31) == 0) sm[threadIdx.x >> 5] = wm;
    __syncthreads();
    if (threadIdx.x == 0)
        d_edge_q[w][e][q] = sm[0] | sm[1] | sm[2] | sm[3];
}

// ---------------------------------------------------------------------------
// K2: map kernel (unchanged).
// ---------------------------------------------------------------------------
__global__ void __launch_bounds__(256) map_kernel(
    const float* __restrict__ sf,
    const int* __restrict__ pad_left,
    const int* __restrict__ pad_top)
{
    __shared__ int  s_ci[P_MAX];
    __shared__ int  s_cj[P_MAX];
    __shared__ char s_hz[P_MAX];
    __shared__ char s_pass[P_MAX];
    __shared__ int  s_P;
    __shared__ unsigned s_edge[NW][4];

    if (threadIdx.x < NW * 4) {
        int w = threadIdx.x >> 2, e = threadIdx.x & 3;
        s_edge[w][e] = d_edge_q[w][e][0] | d_edge_q[w][e][1] |
                       d_edge_q[w][e][2] | d_edge_q[w][e][3];
    }

    if (threadIdx.x == 0) {
        int pl[NW], pt[NW];
        for (int i = 0; i < NW; i++) { pl[i] = pad_left[i]; pt[i] = pad_top[i]; }

        int na = 0;
        int ai[12], aj[12]; char ah[12];
        for (int i = 0; i < NW; i++) {
            for (int j = i + 1; j < NW; j++) {
                if (pt[i] == pt[j] && abs(pl[i] - pl[j]) == WIN_W) {
                    if (pl[i] < pl[j]) { ai[na] = i; aj[na] = j; }
                    else               { ai[na] = j; aj[na] = i; }
                    ah[na] = 1; na++;
                }
                if (pl[i] == pl[j] && abs(pt[i] - pt[j]) == WIN_H) {
                    if (pt[i] < pt[j]) { ai[na] = i; aj[na] = j; }
                    else               { ai[na] = j; aj[na] = i; }
                    ah[na] = 0; na++;
                }
            }
        }
        int P = 0;
        for (int a = 0; a < na; a++) {
            int si = ai[a] * MPW, sj = aj[a] * MPW;
            for (int ci = si + 1; ci < si + MPW; ci++)
                for (int cj = sj + 1; cj < sj + MPW; cj++) {
                    s_ci[P] = ci; s_cj[P] = cj; s_hz[P] = ah[a]; P++;
                }
        }
        s_P = P;
    }
    __syncthreads();

    int P = s_P;
    for (int p = threadIdx.x; p < P; p += blockDim.x) {
        int ci = s_ci[p], cj = s_cj[p];
        int wi = ci / MPW, wj = cj / MPW;
        int ri = ci % MPW - 1, rj = cj % MPW - 1;
        const float* fi = sf + ((long long)wi * (MPW - 1) + ri) * SLOT_DIM;
        const float* fj = sf + ((long long)wj * (MPW - 1) + rj) * SLOT_DIM;
        float dot = 0.f, ni = 0.f, nj = 0.f;
        #pragma unroll
        for (int k = 0; k < SLOT_DIM; k++) {
            float a = fi[k], b = fj[k];
            dot += a * b; ni += a * a; nj += b * b;
        }
        float sim = dot / ((sqrtf(ni) + 1e-8f) * (sqrtf(nj) + 1e-8f));

        bool ok;
        if (s_hz[p]) {
            ok = ((s_edge[wi][1] >> ci) & 1u) && ((s_edge[wj][0] >> cj) & 1u);
        } else {
            ok = ((s_edge[wi][3] >> ci) & 1u) && ((s_edge[wj][2] >> cj) & 1u);
        }
        s_pass[p] = (ok && sim > SIM_THRESH) ? 1 : 0;
    }
    __syncthreads();

    if (threadIdx.x == 0) {
        int mp[CCH];
        bool merged[CCH];
        for (int c = 0; c < CCH; c++) { mp[c] = c; merged[c] = false; }
        for (int p = 0; p < P; p++) {
            int ci = s_ci[p], cj = s_cj[p];
            if (s_pass[p] && !merged[ci] && !merged[cj]) {
                int keep = min(ci, cj), rem = max(ci, cj);
                for (int c = 0; c < CCH; c++)
                    if (mp[c] == rem) mp[c] = keep;
                merged[rem] = true;
            }
        }
        for (int c = 0; c < CCH; c++) d_map[c] = mp[c];
    }
}

// ---------------------------------------------------------------------------
// K3: warp-specialized fused main pass.
// Producer warp (t>=256): issues one 8KB cp.async.bulk per channel into an
//   8-stage ring, gated only by empty-barrier credits. No block syncs.
// Consumers (t<256): wait full[s], 2x LDS.128, argmax update, arrive empty[s].
// Writes: double-buffered SMEM staging + cp.async.bulk stores (consumers only,
//   named barrier 1 with 256 threads).
// ---------------------------------------------------------------------------
__global__ void __launch_bounds__(NTHR) main_kernel(
    const float* __restrict__ masks,
    float* __restrict__ out)
{
    extern __shared__ __align__(16) float dsm[];
    float* sin  = dsm;                    // NSTAGE * CHUNK floats (64KB)
    float* sout = dsm + NSTAGE * CHUNK;   // 2 * CHUNK floats (16KB)

    __shared__ __align__(8) uint64_t mb_full[NSTAGE];
    __shared__ __align__(8) uint64_t mb_empty[NSTAGE];
    __shared__ int smap[CCH];

    const int t = threadIdx.x;
    if (t < CCH) smap[t] = d_map[t];
    if (t == 0) {
        #pragma unroll
        for (int s = 0; s < NSTAGE; s++) {
            asm volatile("mbarrier.init.shared.b64 [%0], %1;"
                         :: "r"(smem_u32(&mb_full[s])), "r"(1u) : "memory");
            asm volatile("mbarrier.init.shared.b64 [%0], %1;"
                         :: "r"(smem_u32(&mb_empty[s])), "r"((unsigned)NCONS) : "memory");
        }
        asm volatile("fence.proxy.async.shared::cta;" ::: "memory");
    }
    __syncthreads();

    const size_t base = (size_t)blockIdx.x * CHUNK;

    if (t >= NCONS) {
        // ---- producer warp ----
        if (t == NCONS) {       // single producer thread
            for (int c = 0; c < CCH; c++) {
                int s = c & (NSTAGE - 1);
                if (c >= NSTAGE) {
                    // wait for consumers to free this stage
                    uint32_t par = ((unsigned)((c - NSTAGE) / NSTAGE)) & 1u;
                    mbar_wait(smem_u32(&mb_empty[s]), par);
                }
                uint32_t mb = smem_u32(&mb_full[s]);
                uint32_t ds = smem_u32(sin + s * CHUNK);
                const float* src = masks + (size_t)c * HW + base;
                asm volatile("mbarrier.arrive.expect_tx.shared.b64 _, [%0], %1;"
                             :: "r"(mb), "r"((unsigned)(CHUNK * 4)) : "memory");
                asm volatile(
                    "cp.async.bulk.shared::cluster.global.mbarrier::complete_tx::bytes "
                    "[%0], [%1], %2, [%3];"
                    :: "r"(ds), "l"(src), "r"((unsigned)(CHUNK * 4)), "r"(mb) : "memory");
            }
        }
        return;   // producer warp done; consumers handle writes
    }

    // ---- consumers ----
    float best[PPT];
    int   ida[PPT];
    #pragma unroll
    for (int i = 0; i < PPT; i++) { best[i] = -INFINITY; ida[i] = 0; }

    for (int c = 0; c < CCH; c++) {
        int s = c & (NSTAGE - 1);
        uint32_t par = ((unsigned)(c / NSTAGE)) & 1u;
        mbar_wait(smem_u32(&mb_full[s]), par);

        const float4* p = (const float4*)(sin + s * CHUNK + t * PPT);
        float4 a = p[0], b = p[1];
        float v[PPT] = {a.x, a.y, a.z, a.w, b.x, b.y, b.z, b.w};
        #pragma unroll
        for (int i = 0; i < PPT; i++)
            if (v[i] > best[i]) { best[i] = v[i]; ida[i] = c; }

        asm volatile("mbarrier.arrive.shared.b64 _, [%0];"
                     :: "r"(smem_u32(&mb_empty[s])) : "memory");
    }

    #pragma unroll
    for (int i = 0; i < PPT; i++) ida[i] = smap[ida[i]];

    // staged one-hot writes, double-buffered bulk stores (256 consumers only)
    for (int c = 0; c < CCH; c++) {
        int buf = c & 1;
        if (c >= 2) {
            if (t == 0)
                asm volatile("cp.async.bulk.wait_group.read 1;" ::: "memory");
            asm volatile("bar.sync 1, %0;" :: "r"(NCONS) : "memory");
        }
        float4* sb4 = (float4*)(sout + buf * CHUNK + t * PPT);
        float4 o1, o2;
        o1.x = (ida[0] == c) ? 1.0f : 0.0f;
        o1.y = (ida[1] == c) ? 1.0f : 0.0f;
        o1.z = (ida[2] == c) ? 1.0f : 0.0f;
        o1.w = (ida[3] == c) ? 1.0f : 0.0f;
        o2.x = (ida[4] == c) ? 1.0f : 0.0f;
        o2.y = (ida[5] == c) ? 1.0f : 0.0f;
        o2.z = (ida[6] == c) ? 1.0f : 0.0f;
        o2.w = (ida[7] == c) ? 1.0f : 0.0f;
        sb4[0] = o1; sb4[1] = o2;
        asm volatile("bar.sync 1, %0;" :: "r"(NCONS) : "memory");
        if (t == 0) {
            float* gdst = out + (size_t)c * HW + base;
            uint32_t saddr = smem_u32(sout + buf * CHUNK);
            asm volatile("fence.proxy.async.shared::cta;" ::: "memory");
            asm volatile(
                "cp.async.bulk.global.shared::cta.bulk_group [%0], [%1], %2;"
                :: "l"(gdst), "r"(saddr), "n"(CHUNK * 4) : "memory");
            asm volatile("cp.async.bulk.commit_group;" ::: "memory");
        }
    }
    if (t == 0)
        asm volatile("cp.async.bulk.wait_group.read 0;" ::: "memory");
}

// ---------------------------------------------------------------------------
extern "C" void kernel_launch(void* const* d_in, const int* in_sizes, int n_in,
                              void* d_out, int out_size)
{
    const float* masks = (const float*)d_in[0];
    const float* sf    = (const float*)d_in[1];
    const int*   pl    = (const int*)d_in[2];
    const int*   pt    = (const int*)d_in[3];
    float*       out   = (float*)d_out;

    static bool configured = false;
    if (!configured) {
        cudaFuncSetAttribute(main_kernel,
                             cudaFuncAttributeMaxDynamicSharedMemorySize,
                             (NSTAGE + 2) * CHUNK * 4);
        configured = true;
    }

    edge_kernel<<<NW * 4 * 4, 128>>>(masks, pl, pt);
    map_kernel<<<1, 256>>>(sf, pl, pt);
    main_kernel<<<HW / CHUNK, NTHR, (NSTAGE + 2) * CHUNK * 4>>>(masks, out);
}